// round 1
// baseline (speedup 1.0000x reference)
#include <cuda_runtime.h>
#include <cstdint>

#define NV   120000
#define ND   30000
#define NV2  60000
#define NPTS 400000
#define CH   128
#define HH   64

// ---------------- scratch (device globals; no allocations allowed) ----------------
__device__ __align__(16) float  g_dssum[(size_t)ND * CH];
__device__ __align__(16) float  g_cntd[ND];
__device__ __align__(16) float  g_identity[(size_t)NV * CH];
__device__ __align__(16) float  g_h1[(size_t)ND * HH];
__device__ __align__(16) float  g_h2[(size_t)ND * HH];
__device__ __align__(16) float  g_h3[(size_t)ND * CH];
__device__ double g_s1[HH], g_q1[HH], g_s2[HH], g_q2[HH];
__device__ __align__(16) float  g_a1[HH], g_b1p[HH], g_a2[HH], g_b2p[HH];
__device__ __align__(16) float  g_t[(size_t)NV * CH];
__device__ __align__(16) float  g_qbuf[(size_t)NV * CH];
__device__ __align__(16) float  g_psum[(size_t)NV2 * CH];
__device__ __align__(16) float  g_cnt2[NV2];

static inline int cdiv(int a, int b) { return (a + b - 1) / b; }

// ---------------- zero scratch ----------------
__global__ void zero_k() {
    int i = blockIdx.x * blockDim.x + threadIdx.x;   // grid covers NV2*CH = 7,680,000 exactly
    if (i < NV2 * CH) g_psum[i] = 0.f;
    if (i < ND * CH)  g_dssum[i] = 0.f;
    if (i < ND)       g_cntd[i] = 0.f;
    if (i < NV2)      g_cnt2[i] = 0.f;
    if (i < HH) { g_s1[i] = 0.0; g_q1[i] = 0.0; g_s2[i] = 0.0; g_q2[i] = 0.0; }
}

// ---------------- scatter x = features + v_fea into ds_sum / counts ----------------
__global__ void scatter_x_k(const float* __restrict__ f, const float* __restrict__ vf,
                            const int* __restrict__ invp,
                            float* __restrict__ dssum, float* __restrict__ cntd) {
    int idx = blockIdx.x * blockDim.x + threadIdx.x;
    if (idx >= NV * (CH / 4)) return;
    int row = idx >> 5;          // CH/4 = 32 float4 per row
    int c4  = idx & 31;
    const float4 a = *(const float4*)&f[(size_t)row * CH + c4 * 4];
    const float4 b = *(const float4*)&vf[(size_t)row * CH + c4 * 4];
    float4 v = make_float4(a.x + b.x, a.y + b.y, a.z + b.z, a.w + b.w);
    int d = invp[row];
    atomicAdd((float4*)&dssum[(size_t)d * CH + c4 * 4], v);   // sm_90+: vector RED
    if (c4 == 0) atomicAdd(&cntd[d], 1.0f);
}

// ---------------- generic fp32 GEMM: C = epi(Asrc @ W + bias) ----------------
// A-source modes
#define M_PLAIN    0
#define M_SUM2     1
#define M_ROWSCALE 2
#define M_COLAFF   3
#define M_CONCAT   4

template<int BM, int N, int K, int AM, bool LRELU>
__global__ void __launch_bounds__(256) gemm_k(
    const float* __restrict__ A0, const float* __restrict__ A1,
    const int*  __restrict__ invp, const float* __restrict__ cntp,
    const float* __restrict__ colA, const float* __restrict__ colB,
    const float* __restrict__ W, const float* __restrict__ bias,
    float* __restrict__ Cout, int M)
{
    constexpr int BK = 32;
    constexpr int TN = N / 16;               // 8 (N=128) or 4 (N=64)
    __shared__ __align__(16) float As[BK * BM];   // XOR-swizzled, transposed: As[k][r]
    __shared__ __align__(16) float Bs[BK * N];

    const int t  = threadIdx.x;
    const int tx = t & 15;                   // column-thread
    const int ty = t >> 4;                   // row-thread (0..15), 4 rows each
    const int row0 = blockIdx.x * BM;

    float acc[4][TN];
#pragma unroll
    for (int i = 0; i < 4; i++)
#pragma unroll
        for (int j = 0; j < TN; j++) acc[i][j] = 0.f;

    for (int kc = 0; kc < K; kc += BK) {
        // ---- load B tile: BK x N ----
#pragma unroll
        for (int i = t; i < BK * N / 4; i += 256) {
            int k = i / (N / 4);
            int n = (i % (N / 4)) * 4;
            *(float4*)&Bs[k * N + n] = *(const float4*)&W[(size_t)(kc + k) * N + n];
        }
        // ---- load A tile (transposed + swizzled): BM rows x BK cols ----
#pragma unroll
        for (int i = t; i < BM * BK / 4; i += 256) {
            int r2 = i >> 3;                 // BK/4 = 8
            int k4 = (i & 7) << 2;
            int grow = row0 + r2;
            int kg = kc + k4;
            float4 v = make_float4(0.f, 0.f, 0.f, 0.f);
            if (grow < M) {
                if constexpr (AM == M_PLAIN) {
                    v = *(const float4*)&A0[(size_t)grow * K + kg];
                } else if constexpr (AM == M_SUM2) {
                    float4 u = *(const float4*)&A0[(size_t)grow * K + kg];
                    float4 w = *(const float4*)&A1[(size_t)grow * K + kg];
                    v = make_float4(u.x + w.x, u.y + w.y, u.z + w.z, u.w + w.w);
                } else if constexpr (AM == M_ROWSCALE) {
                    float rs = 1.0f / fmaxf(cntp[grow], 1.0f);
                    float4 u = *(const float4*)&A0[(size_t)grow * K + kg];
                    v = make_float4(u.x * rs, u.y * rs, u.z * rs, u.w * rs);
                } else if constexpr (AM == M_COLAFF) {
                    float4 u  = *(const float4*)&A0[(size_t)grow * K + kg];
                    float4 ca = *(const float4*)&colA[kg];
                    float4 cb = *(const float4*)&colB[kg];
                    v = make_float4(fmaf(u.x, ca.x, cb.x), fmaf(u.y, ca.y, cb.y),
                                    fmaf(u.z, ca.z, cb.z), fmaf(u.w, ca.w, cb.w));
                } else { // M_CONCAT: [A0 row | A1[inv[row]] row], each CH wide
                    if (kg < CH) v = *(const float4*)&A0[(size_t)grow * CH + kg];
                    else         v = *(const float4*)&A1[(size_t)invp[grow] * CH + (kg - CH)];
                }
            }
            int pr = ((((r2 >> 2) ^ (k4 >> 2)) & 15) << 2) + (r2 & 3);
            As[(k4 + 0) * BM + pr] = v.x;
            As[(k4 + 1) * BM + pr] = v.y;
            As[(k4 + 2) * BM + pr] = v.z;
            As[(k4 + 3) * BM + pr] = v.w;
        }
        __syncthreads();

        // ---- compute ----
#pragma unroll 8
        for (int k = 0; k < BK; k++) {
            float4 a = *(const float4*)&As[k * BM + (((ty ^ (k >> 2)) & 15) << 2)];
            float b[TN];
#pragma unroll
            for (int j = 0; j < TN; j += 4)
                *(float4*)&b[j] = *(const float4*)&Bs[k * N + tx * TN + j];
            float av[4] = {a.x, a.y, a.z, a.w};
#pragma unroll
            for (int i = 0; i < 4; i++)
#pragma unroll
                for (int j = 0; j < TN; j++)
                    acc[i][j] = fmaf(av[i], b[j], acc[i][j]);
        }
        __syncthreads();
    }

    // ---- epilogue: bias + optional lrelu, vectorized store ----
#pragma unroll
    for (int i = 0; i < 4; i++) {
        int r = row0 + ty * 4 + i;
        if (r < M) {
#pragma unroll
            for (int j = 0; j < TN; j += 4) {
                int n = tx * TN + j;
                float4 o;
                o.x = acc[i][j + 0] + bias[n + 0];
                o.y = acc[i][j + 1] + bias[n + 1];
                o.z = acc[i][j + 2] + bias[n + 2];
                o.w = acc[i][j + 3] + bias[n + 3];
                if constexpr (LRELU) {
                    o.x = o.x > 0.f ? o.x : 0.1f * o.x;
                    o.y = o.y > 0.f ? o.y : 0.1f * o.y;
                    o.z = o.z > 0.f ? o.z : 0.1f * o.z;
                    o.w = o.w > 0.f ? o.w : 0.1f * o.w;
                }
                *(float4*)&Cout[(size_t)r * N + n] = o;
            }
        }
    }
}

// ---------------- BatchNorm batch statistics (per-column sum / sumsq) ----------------
__global__ void colstats_k(const float* __restrict__ H, int M,
                           double* __restrict__ sum, double* __restrict__ sqsum) {
    int col = threadIdx.x & 63;
    int ry  = threadIdx.x >> 6;            // 0..3
    int r0  = blockIdx.x * 512;
    int rend = min(M, r0 + 512);
    float s = 0.f, s2 = 0.f;
    for (int r = r0 + ry; r < rend; r += 4) {
        float v = H[(size_t)r * HH + col];
        s += v; s2 += v * v;
    }
    __shared__ float sh[256], sh2[256];
    sh[threadIdx.x] = s; sh2[threadIdx.x] = s2;
    __syncthreads();
    if (ry == 0) {
        s  = sh[col]  + sh[col + 64]  + sh[col + 128]  + sh[col + 192];
        s2 = sh2[col] + sh2[col + 64] + sh2[col + 128] + sh2[col + 192];
        atomicAdd(&sum[col], (double)s);
        atomicAdd(&sqsum[col], (double)s2);
    }
}

__global__ void bnfin_k(const double* __restrict__ sum, const double* __restrict__ sqsum,
                        const float* __restrict__ g, const float* __restrict__ beta,
                        int M, float* __restrict__ a, float* __restrict__ bp) {
    int c = threadIdx.x;
    if (c >= HH) return;
    double m   = sum[c] / (double)M;
    double var = sqsum[c] / (double)M - m * m;    // biased, matches jnp.var
    float ai = g[c] / sqrtf((float)var + 1e-5f);
    a[c]  = ai;
    bp[c] = beta[c] - (float)m * ai;
}

// ---------------- scatter q[cil[p]] into p_sum / counts at next scale ----------------
__global__ void scatter_pts_k(const float* __restrict__ q,
                              const int* __restrict__ cil, const int* __restrict__ cin,
                              float* __restrict__ psum, float* __restrict__ cnt2) {
    int idx = blockIdx.x * blockDim.x + threadIdx.x;
    if (idx >= NPTS * (CH / 4)) return;
    int p = idx >> 5;
    int l = idx & 31;
    int v = cil[p];
    int j = cin[p];
    float4 val = *(const float4*)&q[(size_t)v * CH + l * 4];
    atomicAdd((float4*)&psum[(size_t)j * CH + l * 4], val);
    if (l == 0) atomicAdd(&cnt2[j], 1.0f);
}

// ---------------- final: out[p] = p_sum[cin[p]] / max(cnt,1) ----------------
__global__ void gather_out_k(const float* __restrict__ psum, const float* __restrict__ cnt2,
                             const int* __restrict__ cin, float* __restrict__ out) {
    int idx = blockIdx.x * blockDim.x + threadIdx.x;
    if (idx >= NPTS * (CH / 4)) return;
    int p = idx >> 5;
    int l = idx & 31;
    int j = cin[p];
    float ic = 1.0f / fmaxf(cnt2[j], 1.0f);
    float4 v = *(const float4*)&psum[(size_t)j * CH + l * 4];
    v.x *= ic; v.y *= ic; v.z *= ic; v.w *= ic;
    *(float4*)&out[(size_t)p * CH + l * 4] = v;
}

// ---------------- launch ----------------
extern "C" void kernel_launch(void* const* d_in, const int* in_sizes, int n_in,
                              void* d_out, int out_size) {
    const float* features = (const float*)d_in[0];
    const float* vfea     = (const float*)d_in[1];
    const int*   invp     = (const int*)d_in[2];
    const int*   cil      = (const int*)d_in[3];
    const int*   cin      = (const int*)d_in[4];
    const float* W_in = (const float*)d_in[5];  const float* b_in = (const float*)d_in[6];
    const float* W1   = (const float*)d_in[7];  const float* b1   = (const float*)d_in[8];
    const float* g1   = (const float*)d_in[9];  const float* be1  = (const float*)d_in[10];
    const float* W2   = (const float*)d_in[11]; const float* b2   = (const float*)d_in[12];
    const float* g2   = (const float*)d_in[13]; const float* be2  = (const float*)d_in[14];
    const float* W3   = (const float*)d_in[15]; const float* b3   = (const float*)d_in[16];
    const float* Wo1  = (const float*)d_in[17]; const float* bo1  = (const float*)d_in[18];
    const float* Wo2  = (const float*)d_in[19]; const float* bo2  = (const float*)d_in[20];
    float* out = (float*)d_out;

    float *dssum, *cntd, *ident, *h1, *h2, *h3, *a1, *b1p, *a2, *b2p, *tbuf, *qbuf, *psum, *cnt2;
    double *s1, *q1, *s2, *q2;
    cudaGetSymbolAddress((void**)&dssum, g_dssum);
    cudaGetSymbolAddress((void**)&cntd,  g_cntd);
    cudaGetSymbolAddress((void**)&ident, g_identity);
    cudaGetSymbolAddress((void**)&h1,    g_h1);
    cudaGetSymbolAddress((void**)&h2,    g_h2);
    cudaGetSymbolAddress((void**)&h3,    g_h3);
    cudaGetSymbolAddress((void**)&s1,    g_s1);
    cudaGetSymbolAddress((void**)&q1,    g_q1);
    cudaGetSymbolAddress((void**)&s2,    g_s2);
    cudaGetSymbolAddress((void**)&q2,    g_q2);
    cudaGetSymbolAddress((void**)&a1,    g_a1);
    cudaGetSymbolAddress((void**)&b1p,   g_b1p);
    cudaGetSymbolAddress((void**)&a2,    g_a2);
    cudaGetSymbolAddress((void**)&b2p,   g_b2p);
    cudaGetSymbolAddress((void**)&tbuf,  g_t);
    cudaGetSymbolAddress((void**)&qbuf,  g_qbuf);
    cudaGetSymbolAddress((void**)&psum,  g_psum);
    cudaGetSymbolAddress((void**)&cnt2,  g_cnt2);

    // 1. zero accumulators
    zero_k<<<30000, 256>>>();

    // 2. x = features + v_fea, scatter-mean numerators into downsampled cells
    scatter_x_k<<<cdiv(NV * 32, 256), 256>>>(features, vfea, invp, dssum, cntd);

    // 3. identity = lrelu((features+vfea) @ W_in + b_in)      [NV,128]
    gemm_k<64, 128, 128, M_SUM2, true><<<NV / 64, 256>>>(
        features, vfea, nullptr, nullptr, nullptr, nullptr, W_in, b_in, ident, NV);

    // 4. h1 = lrelu(ds @ W1 + b1)                             [ND,64]
    gemm_k<64, 64, 128, M_ROWSCALE, true><<<cdiv(ND, 64), 256>>>(
        dssum, nullptr, nullptr, cntd, nullptr, nullptr, W1, b1, h1, ND);

    // 5. BN1 stats + fold
    colstats_k<<<cdiv(ND, 512), 256>>>(h1, ND, s1, q1);
    bnfin_k<<<1, 64>>>(s1, q1, g1, be1, ND, a1, b1p);

    // 6. h2 = lrelu(bn1(h1) @ W2 + b2)                        [ND,64]
    gemm_k<64, 64, 64, M_COLAFF, true><<<cdiv(ND, 64), 256>>>(
        h1, nullptr, nullptr, nullptr, a1, b1p, W2, b2, h2, ND);

    // 7. BN2 stats + fold
    colstats_k<<<cdiv(ND, 512), 256>>>(h2, ND, s2, q2);
    bnfin_k<<<1, 64>>>(s2, q2, g2, be2, ND, a2, b2p);

    // 8. h3 = lrelu(bn2(h2) @ W3 + b3)                        [ND,128]
    gemm_k<64, 128, 64, M_COLAFF, true><<<cdiv(ND, 64), 256>>>(
        h2, nullptr, nullptr, nullptr, a2, b2p, W3, b3, h3, ND);

    // 9. t = lrelu([identity | h3[inv]] @ Wo1 + bo1)          [NV,128], K=256
    gemm_k<64, 128, 256, M_CONCAT, true><<<NV / 64, 256>>>(
        ident, h3, invp, nullptr, nullptr, nullptr, Wo1, bo1, tbuf, NV);

    // 10. q = t @ Wo2 + bo2                                   [NV,128]
    gemm_k<64, 128, 128, M_PLAIN, false><<<NV / 64, 256>>>(
        tbuf, nullptr, nullptr, nullptr, nullptr, nullptr, Wo2, bo2, qbuf, NV);

    // 11. segment-sum q[cil] by cin (next-scale voxelization)
    scatter_pts_k<<<cdiv(NPTS * 32, 256), 256>>>(qbuf, cil, cin, psum, cnt2);

    // 12. out = p_fea[cin]
    gather_out_k<<<cdiv(NPTS * 32, 256), 256>>>(psum, cnt2, cin, out);
}

// round 11
// speedup vs baseline: 1.4908x; 1.4908x over previous
#include <cuda_runtime.h>
#include <cstdint>

#define NV   120000
#define ND   30000
#define NV2  60000
#define NPTS 400000
#define CH   128
#define HH   64

// ---------------- scratch (device globals; no allocations allowed) ----------------
__device__ __align__(16) float  g_dssum[(size_t)ND * CH];
__device__ __align__(16) float  g_cntd[ND];
__device__ __align__(16) float  g_identity[(size_t)NV * CH];
__device__ __align__(16) float  g_h1[(size_t)ND * HH];
__device__ __align__(16) float  g_h2[(size_t)ND * HH];
__device__ __align__(16) float  g_h3[(size_t)ND * CH];
__device__ double g_s1[HH], g_q1[HH], g_s2[HH], g_q2[HH];
__device__ __align__(16) float  g_a1[HH], g_b1p[HH], g_a2[HH], g_b2p[HH];
__device__ __align__(16) float  g_t[(size_t)NV * CH];
__device__ __align__(16) float  g_qbuf[(size_t)NV * CH];
__device__ __align__(16) float  g_psum[(size_t)NV2 * CH];
__device__ __align__(16) float  g_cnt2[NV2];

static inline int cdiv(int a, int b) { return (a + b - 1) / b; }

__device__ __forceinline__ float tf32_rna(float x) {
    float r;
    asm("cvt.rna.tf32.f32 %0, %1;" : "=f"(r) : "f"(x));
    return r;
}

// m16n8k8 tf32 mma: D = A@B + D  (A row-major m16k8, B col-frag k8n8)
__device__ __forceinline__ void mma_tf32(float* d, const uint32_t* a, const uint32_t* b) {
    asm volatile(
        "mma.sync.aligned.m16n8k8.row.col.f32.tf32.tf32.f32 "
        "{%0,%1,%2,%3}, {%4,%5,%6,%7}, {%8,%9}, {%0,%1,%2,%3};"
        : "+f"(d[0]), "+f"(d[1]), "+f"(d[2]), "+f"(d[3])
        : "r"(a[0]), "r"(a[1]), "r"(a[2]), "r"(a[3]), "r"(b[0]), "r"(b[1]));
}

// ---------------- zero scratch ----------------
__global__ void zero_k() {
    int i = blockIdx.x * blockDim.x + threadIdx.x;
    if (i < NV2 * CH) g_psum[i] = 0.f;
    if (i < ND * CH)  g_dssum[i] = 0.f;
    if (i < ND)       g_cntd[i] = 0.f;
    if (i < NV2)      g_cnt2[i] = 0.f;
    if (i < HH) { g_s1[i] = 0.0; g_q1[i] = 0.0; g_s2[i] = 0.0; g_q2[i] = 0.0; }
}

// ---------------- scatter x = features + v_fea into ds_sum / counts ----------------
__global__ void scatter_x_k(const float* __restrict__ f, const float* __restrict__ vf,
                            const int* __restrict__ invp,
                            float* __restrict__ dssum, float* __restrict__ cntd) {
    int idx = blockIdx.x * blockDim.x + threadIdx.x;
    if (idx >= NV * (CH / 4)) return;
    int row = idx >> 5;
    int c4  = idx & 31;
    const float4 a = *(const float4*)&f[(size_t)row * CH + c4 * 4];
    const float4 b = *(const float4*)&vf[(size_t)row * CH + c4 * 4];
    float4 v = make_float4(a.x + b.x, a.y + b.y, a.z + b.z, a.w + b.w);
    int d = invp[row];
    atomicAdd((float4*)&dssum[(size_t)d * CH + c4 * 4], v);
    if (c4 == 0) atomicAdd(&cntd[d], 1.0f);
}

// ============ tensor-core split-tf32 GEMM via mma.sync: C[M,128] = epi(A@W + b) ====
// fp32 emulated as 3xTF32: A=Ah+Al, B=Bh+Bl; acc += Ah*Bh + Ah*Bl + Al*Bh.
#define M_PLAIN    0
#define M_SUM2     1
#define M_CONCAT   4
#define M_ROWSCALE 2
#define M_COLAFF   3

// SMEM (floats): Ah[128][36], Al[128][36], Bh[32][136], Bl[32][136]
static constexpr int AS_STRIDE = 36;
static constexpr int BS_STRIDE = 136;
static constexpr int SM_AH = 0;
static constexpr int SM_AL = 128 * AS_STRIDE;
static constexpr int SM_BH = 2 * 128 * AS_STRIDE;
static constexpr int SM_BL = SM_BH + 32 * BS_STRIDE;
static constexpr int SMEM_MMA_FLOATS = SM_BL + 32 * BS_STRIDE;
static constexpr int SMEM_MMA_BYTES  = SMEM_MMA_FLOATS * 4;   // 71680

template<int KTOT, int AM, bool LRELU>
__global__ void __launch_bounds__(256) gemm_mma(
    const float* __restrict__ A0, const float* __restrict__ A1,
    const int* __restrict__ invp,
    const float* __restrict__ W, const float* __restrict__ bias,
    float* __restrict__ Cout, int M)
{
    extern __shared__ float sm[];
    const int t    = threadIdx.x;
    const int warp = t >> 5;
    const int lane = t & 31;
    const int g    = lane >> 2;    // group 0..7
    const int tig  = lane & 3;     // thread-in-group
    const int rw0  = (warp >> 1) * 32;   // warp M offset (4 warps in M)
    const int nw0  = (warp & 1) * 64;    // warp N offset (2 warps in N)
    const int row0 = blockIdx.x * 128;

    float acc[2][8][4];
    #pragma unroll
    for (int mt = 0; mt < 2; mt++)
        #pragma unroll
        for (int nt = 0; nt < 8; nt++)
            #pragma unroll
            for (int i = 0; i < 4; i++) acc[mt][nt][i] = 0.f;

    for (int kc = 0; kc < KTOT; kc += 32) {
        // ---- stage A tile 128x32 (fused source, split hi/lo) ----
        #pragma unroll
        for (int i = t; i < 128 * 8; i += 256) {
            int row = i >> 3;
            int k4  = (i & 7) << 2;
            int grow = row0 + row;
            int col  = kc + k4;
            float4 v = make_float4(0.f, 0.f, 0.f, 0.f);
            if (grow < M) {
                if constexpr (AM == M_SUM2) {
                    float4 u = *(const float4*)&A0[(size_t)grow * 128 + col];
                    float4 w = *(const float4*)&A1[(size_t)grow * 128 + col];
                    v = make_float4(u.x + w.x, u.y + w.y, u.z + w.z, u.w + w.w);
                } else if constexpr (AM == M_CONCAT) {
                    if (col < 128) v = *(const float4*)&A0[(size_t)grow * 128 + col];
                    else           v = *(const float4*)&A1[(size_t)invp[grow] * 128 + (col - 128)];
                } else { // M_PLAIN
                    v = *(const float4*)&A0[(size_t)grow * KTOT + col];
                }
            }
            float4 h = make_float4(tf32_rna(v.x), tf32_rna(v.y), tf32_rna(v.z), tf32_rna(v.w));
            float4 l = make_float4(tf32_rna(v.x - h.x), tf32_rna(v.y - h.y),
                                   tf32_rna(v.z - h.z), tf32_rna(v.w - h.w));
            *(float4*)&sm[SM_AH + row * AS_STRIDE + k4] = h;
            *(float4*)&sm[SM_AL + row * AS_STRIDE + k4] = l;
        }
        // ---- stage W tile 32x128 (split hi/lo) ----
        #pragma unroll
        for (int i = t; i < 32 * 32; i += 256) {
            int k  = i >> 5;
            int n4 = (i & 31) << 2;
            float4 v = *(const float4*)&W[(size_t)(kc + k) * 128 + n4];
            float4 h = make_float4(tf32_rna(v.x), tf32_rna(v.y), tf32_rna(v.z), tf32_rna(v.w));
            float4 l = make_float4(tf32_rna(v.x - h.x), tf32_rna(v.y - h.y),
                                   tf32_rna(v.z - h.z), tf32_rna(v.w - h.w));
            *(float4*)&sm[SM_BH + k * BS_STRIDE + n4] = h;
            *(float4*)&sm[SM_BL + k * BS_STRIDE + n4] = l;
        }
        __syncthreads();

        // ---- compute: 4 k8-steps per chunk ----
        #pragma unroll
        for (int k8 = 0; k8 < 4; k8++) {
            int ks = k8 * 8;
            uint32_t bh[8][2], bl[8][2];
            #pragma unroll
            for (int nt = 0; nt < 8; nt++) {
                int col = nw0 + nt * 8 + g;
                bh[nt][0] = __float_as_uint(sm[SM_BH + (ks + tig)     * BS_STRIDE + col]);
                bh[nt][1] = __float_as_uint(sm[SM_BH + (ks + tig + 4) * BS_STRIDE + col]);
                bl[nt][0] = __float_as_uint(sm[SM_BL + (ks + tig)     * BS_STRIDE + col]);
                bl[nt][1] = __float_as_uint(sm[SM_BL + (ks + tig + 4) * BS_STRIDE + col]);
            }
            #pragma unroll
            for (int mt = 0; mt < 2; mt++) {
                int r = rw0 + mt * 16 + g;
                uint32_t ah[4], al[4];
                ah[0] = __float_as_uint(sm[SM_AH + r       * AS_STRIDE + ks + tig]);
                ah[1] = __float_as_uint(sm[SM_AH + (r + 8) * AS_STRIDE + ks + tig]);
                ah[2] = __float_as_uint(sm[SM_AH + r       * AS_STRIDE + ks + tig + 4]);
                ah[3] = __float_as_uint(sm[SM_AH + (r + 8) * AS_STRIDE + ks + tig + 4]);
                al[0] = __float_as_uint(sm[SM_AL + r       * AS_STRIDE + ks + tig]);
                al[1] = __float_as_uint(sm[SM_AL + (r + 8) * AS_STRIDE + ks + tig]);
                al[2] = __float_as_uint(sm[SM_AL + r       * AS_STRIDE + ks + tig + 4]);
                al[3] = __float_as_uint(sm[SM_AL + (r + 8) * AS_STRIDE + ks + tig + 4]);
                #pragma unroll
                for (int nt = 0; nt < 8; nt++) {
                    mma_tf32(acc[mt][nt], ah, bh[nt]);
                    mma_tf32(acc[mt][nt], ah, bl[nt]);
                    mma_tf32(acc[mt][nt], al, bh[nt]);
                }
            }
        }
        __syncthreads();
    }

    // ---- epilogue: bias + lrelu, float2 stores ----
    #pragma unroll
    for (int mt = 0; mt < 2; mt++) {
        int rbase = row0 + rw0 + mt * 16 + g;
        #pragma unroll
        for (int nt = 0; nt < 8; nt++) {
            int c = nw0 + nt * 8 + tig * 2;
            float b0 = __ldg(&bias[c]), b1 = __ldg(&bias[c + 1]);
            if (rbase < M) {
                float2 o;
                o.x = acc[mt][nt][0] + b0;
                o.y = acc[mt][nt][1] + b1;
                if constexpr (LRELU) {
                    o.x = o.x > 0.f ? o.x : 0.1f * o.x;
                    o.y = o.y > 0.f ? o.y : 0.1f * o.y;
                }
                *(float2*)&Cout[(size_t)rbase * 128 + c] = o;
            }
            if (rbase + 8 < M) {
                float2 o;
                o.x = acc[mt][nt][2] + b0;
                o.y = acc[mt][nt][3] + b1;
                if constexpr (LRELU) {
                    o.x = o.x > 0.f ? o.x : 0.1f * o.x;
                    o.y = o.y > 0.f ? o.y : 0.1f * o.y;
                }
                *(float2*)&Cout[(size_t)(rbase + 8) * 128 + c] = o;
            }
        }
    }
}

// ---------------- SIMT fp32 GEMM (small ND GEMMs) ----------------
template<int BM, int N, int K, int AM, bool LRELU>
__global__ void __launch_bounds__(256) gemm_k(
    const float* __restrict__ A0, const float* __restrict__ A1,
    const int*  __restrict__ invp, const float* __restrict__ cntp,
    const float* __restrict__ colA, const float* __restrict__ colB,
    const float* __restrict__ W, const float* __restrict__ bias,
    float* __restrict__ Cout, int M)
{
    constexpr int BK = 32;
    constexpr int TN = N / 16;
    __shared__ __align__(16) float As[BK * BM];
    __shared__ __align__(16) float Bs[BK * N];

    const int t  = threadIdx.x;
    const int tx = t & 15;
    const int ty = t >> 4;
    const int row0 = blockIdx.x * BM;

    float acc[4][TN];
#pragma unroll
    for (int i = 0; i < 4; i++)
#pragma unroll
        for (int j = 0; j < TN; j++) acc[i][j] = 0.f;

    for (int kc = 0; kc < K; kc += BK) {
#pragma unroll
        for (int i = t; i < BK * N / 4; i += 256) {
            int k = i / (N / 4);
            int n = (i % (N / 4)) * 4;
            *(float4*)&Bs[k * N + n] = *(const float4*)&W[(size_t)(kc + k) * N + n];
        }
#pragma unroll
        for (int i = t; i < BM * BK / 4; i += 256) {
            int r2 = i >> 3;
            int k4 = (i & 7) << 2;
            int grow = row0 + r2;
            int kg = kc + k4;
            float4 v = make_float4(0.f, 0.f, 0.f, 0.f);
            if (grow < M) {
                if constexpr (AM == M_ROWSCALE) {
                    float rs = 1.0f / fmaxf(cntp[grow], 1.0f);
                    float4 u = *(const float4*)&A0[(size_t)grow * K + kg];
                    v = make_float4(u.x * rs, u.y * rs, u.z * rs, u.w * rs);
                } else if constexpr (AM == M_COLAFF) {
                    float4 u  = *(const float4*)&A0[(size_t)grow * K + kg];
                    float4 ca = *(const float4*)&colA[kg];
                    float4 cb = *(const float4*)&colB[kg];
                    v = make_float4(fmaf(u.x, ca.x, cb.x), fmaf(u.y, ca.y, cb.y),
                                    fmaf(u.z, ca.z, cb.z), fmaf(u.w, ca.w, cb.w));
                } else {
                    v = *(const float4*)&A0[(size_t)grow * K + kg];
                }
            }
            int pr = ((((r2 >> 2) ^ (k4 >> 2)) & 15) << 2) + (r2 & 3);
            As[(k4 + 0) * BM + pr] = v.x;
            As[(k4 + 1) * BM + pr] = v.y;
            As[(k4 + 2) * BM + pr] = v.z;
            As[(k4 + 3) * BM + pr] = v.w;
        }
        __syncthreads();

#pragma unroll 8
        for (int k = 0; k < BK; k++) {
            float4 a = *(const float4*)&As[k * BM + (((ty ^ (k >> 2)) & 15) << 2)];
            float b[TN];
#pragma unroll
            for (int j = 0; j < TN; j += 4)
                *(float4*)&b[j] = *(const float4*)&Bs[k * N + tx * TN + j];
            float av[4] = {a.x, a.y, a.z, a.w};
#pragma unroll
            for (int i = 0; i < 4; i++)
#pragma unroll
                for (int j = 0; j < TN; j++)
                    acc[i][j] = fmaf(av[i], b[j], acc[i][j]);
        }
        __syncthreads();
    }

#pragma unroll
    for (int i = 0; i < 4; i++) {
        int r = row0 + ty * 4 + i;
        if (r < M) {
#pragma unroll
            for (int j = 0; j < TN; j += 4) {
                int n = tx * TN + j;
                float4 o;
                o.x = acc[i][j + 0] + bias[n + 0];
                o.y = acc[i][j + 1] + bias[n + 1];
                o.z = acc[i][j + 2] + bias[n + 2];
                o.w = acc[i][j + 3] + bias[n + 3];
                if constexpr (LRELU) {
                    o.x = o.x > 0.f ? o.x : 0.1f * o.x;
                    o.y = o.y > 0.f ? o.y : 0.1f * o.y;
                    o.z = o.z > 0.f ? o.z : 0.1f * o.z;
                    o.w = o.w > 0.f ? o.w : 0.1f * o.w;
                }
                *(float4*)&Cout[(size_t)r * N + n] = o;
            }
        }
    }
}

// ---------------- BatchNorm batch statistics ----------------
__global__ void colstats_k(const float* __restrict__ H, int M,
                           double* __restrict__ sum, double* __restrict__ sqsum) {
    int col = threadIdx.x & 63;
    int ry  = threadIdx.x >> 6;
    int r0  = blockIdx.x * 512;
    int rend = min(M, r0 + 512);
    float s = 0.f, s2 = 0.f;
    for (int r = r0 + ry; r < rend; r += 4) {
        float v = H[(size_t)r * HH + col];
        s += v; s2 += v * v;
    }
    __shared__ float sh[256], sh2[256];
    sh[threadIdx.x] = s; sh2[threadIdx.x] = s2;
    __syncthreads();
    if (ry == 0) {
        s  = sh[col]  + sh[col + 64]  + sh[col + 128]  + sh[col + 192];
        s2 = sh2[col] + sh2[col + 64] + sh2[col + 128] + sh2[col + 192];
        atomicAdd(&sum[col], (double)s);
        atomicAdd(&sqsum[col], (double)s2);
    }
}

__global__ void bnfin_k(const double* __restrict__ sum, const double* __restrict__ sqsum,
                        const float* __restrict__ g, const float* __restrict__ beta,
                        int M, float* __restrict__ a, float* __restrict__ bp) {
    int c = threadIdx.x;
    if (c >= HH) return;
    double m   = sum[c] / (double)M;
    double var = sqsum[c] / (double)M - m * m;
    float ai = g[c] / sqrtf((float)var + 1e-5f);
    a[c]  = ai;
    bp[c] = beta[c] - (float)m * ai;
}

// ---------------- scatter q[cil[p]] into p_sum / counts ----------------
__global__ void scatter_pts_k(const float* __restrict__ q,
                              const int* __restrict__ cil, const int* __restrict__ cin,
                              float* __restrict__ psum, float* __restrict__ cnt2) {
    int idx = blockIdx.x * blockDim.x + threadIdx.x;
    if (idx >= NPTS * (CH / 4)) return;
    int p = idx >> 5;
    int l = idx & 31;
    int v = cil[p];
    int j = cin[p];
    float4 val = *(const float4*)&q[(size_t)v * CH + l * 4];
    atomicAdd((float4*)&psum[(size_t)j * CH + l * 4], val);
    if (l == 0) atomicAdd(&cnt2[j], 1.0f);
}

// ---------------- final gather ----------------
__global__ void gather_out_k(const float* __restrict__ psum, const float* __restrict__ cnt2,
                             const int* __restrict__ cin, float* __restrict__ out) {
    int idx = blockIdx.x * blockDim.x + threadIdx.x;
    if (idx >= NPTS * (CH / 4)) return;
    int p = idx >> 5;
    int l = idx & 31;
    int j = cin[p];
    float ic = 1.0f / fmaxf(cnt2[j], 1.0f);
    float4 v = *(const float4*)&psum[(size_t)j * CH + l * 4];
    v.x *= ic; v.y *= ic; v.z *= ic; v.w *= ic;
    *(float4*)&out[(size_t)p * CH + l * 4] = v;
}

// ---------------- launch ----------------
extern "C" void kernel_launch(void* const* d_in, const int* in_sizes, int n_in,
                              void* d_out, int out_size) {
    const float* features = (const float*)d_in[0];
    const float* vfea     = (const float*)d_in[1];
    const int*   invp     = (const int*)d_in[2];
    const int*   cil      = (const int*)d_in[3];
    const int*   cin      = (const int*)d_in[4];
    const float* W_in = (const float*)d_in[5];  const float* b_in = (const float*)d_in[6];
    const float* W1   = (const float*)d_in[7];  const float* b1   = (const float*)d_in[8];
    const float* g1   = (const float*)d_in[9];  const float* be1  = (const float*)d_in[10];
    const float* W2   = (const float*)d_in[11]; const float* b2   = (const float*)d_in[12];
    const float* g2   = (const float*)d_in[13]; const float* be2  = (const float*)d_in[14];
    const float* W3   = (const float*)d_in[15]; const float* b3   = (const float*)d_in[16];
    const float* Wo1  = (const float*)d_in[17]; const float* bo1  = (const float*)d_in[18];
    const float* Wo2  = (const float*)d_in[19]; const float* bo2  = (const float*)d_in[20];
    float* out = (float*)d_out;

    float *dssum, *cntd, *ident, *h1, *h2, *h3, *a1, *b1p, *a2, *b2p, *tbuf, *qbuf, *psum, *cnt2;
    double *s1, *q1, *s2, *q2;
    cudaGetSymbolAddress((void**)&dssum, g_dssum);
    cudaGetSymbolAddress((void**)&cntd,  g_cntd);
    cudaGetSymbolAddress((void**)&ident, g_identity);
    cudaGetSymbolAddress((void**)&h1,    g_h1);
    cudaGetSymbolAddress((void**)&h2,    g_h2);
    cudaGetSymbolAddress((void**)&h3,    g_h3);
    cudaGetSymbolAddress((void**)&s1,    g_s1);
    cudaGetSymbolAddress((void**)&q1,    g_q1);
    cudaGetSymbolAddress((void**)&s2,    g_s2);
    cudaGetSymbolAddress((void**)&q2,    g_q2);
    cudaGetSymbolAddress((void**)&a1,    g_a1);
    cudaGetSymbolAddress((void**)&b1p,   g_b1p);
    cudaGetSymbolAddress((void**)&a2,    g_a2);
    cudaGetSymbolAddress((void**)&b2p,   g_b2p);
    cudaGetSymbolAddress((void**)&tbuf,  g_t);
    cudaGetSymbolAddress((void**)&qbuf,  g_qbuf);
    cudaGetSymbolAddress((void**)&psum,  g_psum);
    cudaGetSymbolAddress((void**)&cnt2,  g_cnt2);

    cudaFuncSetAttribute(gemm_mma<128, M_SUM2,  true>,
                         cudaFuncAttributeMaxDynamicSharedMemorySize, SMEM_MMA_BYTES);
    cudaFuncSetAttribute(gemm_mma<256, M_CONCAT, true>,
                         cudaFuncAttributeMaxDynamicSharedMemorySize, SMEM_MMA_BYTES);
    cudaFuncSetAttribute(gemm_mma<128, M_PLAIN, false>,
                         cudaFuncAttributeMaxDynamicSharedMemorySize, SMEM_MMA_BYTES);

    // 1. zero accumulators
    zero_k<<<30000, 256>>>();

    // 2. scatter-mean numerators for downsample
    scatter_x_k<<<cdiv(NV * 32, 256), 256>>>(features, vfea, invp, dssum, cntd);

    // 3. identity = lrelu((features+vfea) @ W_in + b_in)    [NV,128]  (tensor mma.sync)
    gemm_mma<128, M_SUM2, true><<<cdiv(NV, 128), 256, SMEM_MMA_BYTES>>>(
        features, vfea, nullptr, W_in, b_in, ident, NV);

    // 4. h1 = lrelu(ds @ W1 + b1)                           [ND,64]  (SIMT)
    gemm_k<64, 64, 128, M_ROWSCALE, true><<<cdiv(ND, 64), 256>>>(
        dssum, nullptr, nullptr, cntd, nullptr, nullptr, W1, b1, h1, ND);

    // 5. BN1 stats + fold
    colstats_k<<<cdiv(ND, 512), 256>>>(h1, ND, s1, q1);
    bnfin_k<<<1, 64>>>(s1, q1, g1, be1, ND, a1, b1p);

    // 6. h2 = lrelu(bn1(h1) @ W2 + b2)                      [ND,64]  (SIMT)
    gemm_k<64, 64, 64, M_COLAFF, true><<<cdiv(ND, 64), 256>>>(
        h1, nullptr, nullptr, nullptr, a1, b1p, W2, b2, h2, ND);

    // 7. BN2 stats + fold
    colstats_k<<<cdiv(ND, 512), 256>>>(h2, ND, s2, q2);
    bnfin_k<<<1, 64>>>(s2, q2, g2, be2, ND, a2, b2p);

    // 8. h3 = lrelu(bn2(h2) @ W3 + b3)                      [ND,128] (SIMT)
    gemm_k<64, 128, 64, M_COLAFF, true><<<cdiv(ND, 64), 256>>>(
        h2, nullptr, nullptr, nullptr, a2, b2p, W3, b3, h3, ND);

    // 9. t = lrelu([identity | h3[inv]] @ Wo1 + bo1)        [NV,128], K=256 (tensor)
    gemm_mma<256, M_CONCAT, true><<<cdiv(NV, 128), 256, SMEM_MMA_BYTES>>>(
        ident, h3, invp, Wo1, bo1, tbuf, NV);

    // 10. q = t @ Wo2 + bo2                                 [NV,128] (tensor)
    gemm_mma<128, M_PLAIN, false><<<cdiv(NV, 128), 256, SMEM_MMA_BYTES>>>(
        tbuf, nullptr, nullptr, Wo2, bo2, qbuf, NV);

    // 11. segment-sum q[cil] by cin
    scatter_pts_k<<<cdiv(NPTS * 32, 256), 256>>>(qbuf, cil, cin, psum, cnt2);

    // 12. out = p_fea[cin]
    gather_out_k<<<cdiv(NPTS * 32, 256), 256>>>(psum, cnt2, cin, out);
}